// round 2
// baseline (speedup 1.0000x reference)
#include <cuda_runtime.h>
#include <math.h>

// Problem dims
#define NB 512
#define NT 64
#define NS 30
#define ND 200
#define NH 200
#define NA 12
#define NE 1024
#define OUTC 380   // 6*NS + ND

// Scratch (device globals: allocation-free rule)
__device__ float g_pre_inp[NB * NT * NH];  // action @ inp_W[30:42] + inp_b
__device__ float g_pre_obs[NB * NT * NH];  // embed @ obs_out_W[200:1224] + obs_out_b

// ---------------- packed f32x2 helpers ----------------
__device__ __forceinline__ unsigned long long pack2(float lo, float hi) {
    unsigned long long r;
    asm("mov.b64 %0, {%1, %2};" : "=l"(r) : "f"(lo), "f"(hi));
    return r;
}
__device__ __forceinline__ void unpack2(unsigned long long v, float& lo, float& hi) {
    asm("mov.b64 {%0, %1}, %2;" : "=f"(lo), "=f"(hi) : "l"(v));
}
__device__ __forceinline__ unsigned long long fma2(unsigned long long a,
                                                   unsigned long long b,
                                                   unsigned long long c) {
    unsigned long long d;
    asm("fma.rn.f32x2 %0, %1, %2, %3;" : "=l"(d) : "l"(a), "l"(b), "l"(c));
    return d;
}

// ---------------- math helpers (match jax fp32 semantics) ----------------
__device__ __forceinline__ float eluf(float z)      { return z > 0.f ? z : expm1f(z); }
__device__ __forceinline__ float sigmoidf_(float z) { return 1.f / (1.f + expf(-z)); }
__device__ __forceinline__ float softplusf_(float z){ return fmaxf(z, 0.f) + log1pf(expf(-fabsf(z))); }

// =====================================================================
// Kernel 1: precompute  (parallel over all 32768 (b,t) rows)
//   g_pre_obs[bt][j] = sum_k embed[bt][k] * obs_out_W[(200+k)][j] + obs_out_b[j]
//   g_pre_inp[bt][j] = sum_k action[bt][k] * inp_W[(30+k)][j]     + inp_b[j]
// CTA = 32 bt-rows, 224 threads (j<200 compute), k-chunked smem staging.
// =====================================================================
#define PRE_ROWS 32
#define PRE_KC   256
#define PRE_PAD  36   // row stride in floats: 144B (16B aligned, reduced bank conflicts)

__global__ void __launch_bounds__(224) precompute_kernel(
    const float* __restrict__ embed,
    const float* __restrict__ action,
    const float* __restrict__ obs_out_W,
    const float* __restrict__ obs_out_b,
    const float* __restrict__ inp_W,
    const float* __restrict__ inp_b)
{
    __shared__ __align__(16) float s_aT[PRE_KC * PRE_PAD];  // [kk][row] transposed
    __shared__ float s_act[PRE_ROWS * NA];

    const int bt0 = blockIdx.x * PRE_ROWS;
    const int tid = threadIdx.x;
    const int j   = tid;  // output column, active if < 200

    // 16 packed accumulators: acc[2q] -> rows (4q,4q+1), acc[2q+1] -> rows (4q+2,4q+3)
    unsigned long long acc[16];
    {
        float b = (j < NH) ? obs_out_b[j] : 0.f;
        unsigned long long bb = pack2(b, b);
#pragma unroll
        for (int i = 0; i < 16; i++) acc[i] = bb;
    }

    const float* W2 = obs_out_W + (size_t)ND * NH;  // rows 200..1223

    for (int kc = 0; kc < NE; kc += PRE_KC) {
        __syncthreads();
        // stage embed chunk transposed: s_aT[kk][row]
        for (int idx = tid; idx < PRE_ROWS * PRE_KC; idx += blockDim.x) {
            int rr = idx / PRE_KC;
            int kk = idx % PRE_KC;
            s_aT[kk * PRE_PAD + rr] = embed[(size_t)(bt0 + rr) * NE + kc + kk];
        }
        __syncthreads();

        if (j < NH) {
#pragma unroll 2
            for (int kk = 0; kk < PRE_KC; kk++) {
                float w = W2[(size_t)(kc + kk) * NH + j];
                unsigned long long wv = pack2(w, w);
                const ulonglong2* ap = (const ulonglong2*)&s_aT[kk * PRE_PAD];
#pragma unroll
                for (int q = 0; q < 8; q++) {
                    ulonglong2 a = ap[q];
                    acc[2 * q]     = fma2(a.x, wv, acc[2 * q]);
                    acc[2 * q + 1] = fma2(a.y, wv, acc[2 * q + 1]);
                }
            }
        }
    }

    if (j < NH) {
#pragma unroll
        for (int q = 0; q < 8; q++) {
            float v0, v1, v2, v3;
            unpack2(acc[2 * q],     v0, v1);
            unpack2(acc[2 * q + 1], v2, v3);
            g_pre_obs[(size_t)(bt0 + 4 * q + 0) * NH + j] = v0;
            g_pre_obs[(size_t)(bt0 + 4 * q + 1) * NH + j] = v1;
            g_pre_obs[(size_t)(bt0 + 4 * q + 2) * NH + j] = v2;
            g_pre_obs[(size_t)(bt0 + 4 * q + 3) * NH + j] = v3;
        }
    }

    // ---- pre_inp (tiny: K=12) ----
    __syncthreads();
    for (int idx = tid; idx < PRE_ROWS * NA; idx += blockDim.x) {
        int rr = idx / NA, kk = idx % NA;
        s_act[idx] = action[(size_t)(bt0 + rr) * NA + kk];
    }
    __syncthreads();

    if (j < NH) {
        float ib = inp_b[j];
        float wA[NA];
#pragma unroll
        for (int k = 0; k < NA; k++) wA[k] = inp_W[(NS + k) * NH + j];
        for (int rr = 0; rr < PRE_ROWS; rr++) {
            float a = ib;
#pragma unroll
            for (int k = 0; k < NA; k++) a = fmaf(s_act[rr * NA + k], wA[k], a);
            g_pre_inp[(size_t)(bt0 + rr) * NH + j] = a;
        }
    }
}

// =====================================================================
// Kernel 2: sequential scan. 128 CTAs x 4 batch rows, 256 threads.
// Activations transposed in smem: s_*[k*4 + r].
// =====================================================================
#define R 4

__global__ void __launch_bounds__(256) scan_kernel(
    const float* __restrict__ noise_prior,
    const float* __restrict__ noise_post,
    const float* __restrict__ inp_W,       // rows 0..29 used
    const float* __restrict__ gru_W,       // [400,600]
    const float* __restrict__ gru_b,       // [600]
    const float* __restrict__ img_out_W,   // [200,200]
    const float* __restrict__ img_out_b,
    const float* __restrict__ ims_W,       // [200,60]
    const float* __restrict__ ims_b,
    const float* __restrict__ obs_out_W,   // rows 0..199 (deter part)
    const float* __restrict__ obs_W,       // [200,60]
    const float* __restrict__ obs_b,
    float* __restrict__ out)
{
    __shared__ __align__(16) float s_xd[400 * R];    // k<200: x,  k in [200,400): deter
    __shared__ __align__(16) float s_dn[200 * R];    // deter_new
    __shared__ __align__(16) float s_h [200 * R];
    __shared__ __align__(16) float s_ho[200 * R];
    __shared__ __align__(16) float s_stoch[32 * R];
    __shared__ __align__(16) float s_stat_pr[60 * R];
    __shared__ __align__(16) float s_stat_po[60 * R];

    const int tid  = threadIdx.x;
    const int row0 = blockIdx.x * R;

    for (int i = tid; i < 400 * R; i += 256) s_xd[i] = 0.f;   // zero init deter (x overwritten)
    for (int i = tid; i < 32 * R;  i += 256) s_stoch[i] = 0.f;
    __syncthreads();

    for (int t = 0; t < NT; t++) {
        // ---------- A: x = elu(stoch @ inp_W[:30] + pre_inp) ----------
        if (tid < NH) {
            const int j = tid;
            size_t base = ((size_t)row0 * NT + t) * NH + j;
            unsigned long long a0 = pack2(g_pre_inp[base],
                                          g_pre_inp[base + (size_t)NT * NH]);
            unsigned long long a1 = pack2(g_pre_inp[base + 2 * (size_t)NT * NH],
                                          g_pre_inp[base + 3 * (size_t)NT * NH]);
#pragma unroll
            for (int k = 0; k < NS; k++) {
                float w = inp_W[k * NH + j];
                unsigned long long wv = pack2(w, w);
                ulonglong2 av = *(const ulonglong2*)&s_stoch[k * R];
                a0 = fma2(av.x, wv, a0);
                a1 = fma2(av.y, wv, a1);
            }
            float y0, y1, y2, y3;
            unpack2(a0, y0, y1); unpack2(a1, y2, y3);
            s_xd[j * R + 0] = eluf(y0);
            s_xd[j * R + 1] = eluf(y1);
            s_xd[j * R + 2] = eluf(y2);
            s_xd[j * R + 3] = eluf(y3);
        }
        __syncthreads();

        // ---------- B: GRU (gate-fused: thread u owns cols u, u+200, u+400) ----------
        if (tid < ND) {
            const int u = tid;
            float br = gru_b[u], bc = gru_b[200 + u], bu = gru_b[400 + u];
            unsigned long long pr0 = pack2(br, br), pr1 = pr0;
            unsigned long long pc0 = pack2(bc, bc), pc1 = pc0;
            unsigned long long pu0 = pack2(bu, bu), pu1 = pu0;
            const float* w = gru_W + u;
#pragma unroll 4
            for (int k = 0; k < 400; k++) {
                ulonglong2 av = *(const ulonglong2*)&s_xd[k * R];
                float wr = w[0], wc = w[200], wu = w[400];
                w += 600;
                unsigned long long wrv = pack2(wr, wr);
                unsigned long long wcv = pack2(wc, wc);
                unsigned long long wuv = pack2(wu, wu);
                pr0 = fma2(av.x, wrv, pr0);  pr1 = fma2(av.y, wrv, pr1);
                pc0 = fma2(av.x, wcv, pc0);  pc1 = fma2(av.y, wcv, pc1);
                pu0 = fma2(av.x, wuv, pu0);  pu1 = fma2(av.y, wuv, pu1);
            }
            float rr[R], cc[R], uu[R];
            unpack2(pr0, rr[0], rr[1]); unpack2(pr1, rr[2], rr[3]);
            unpack2(pc0, cc[0], cc[1]); unpack2(pc1, cc[2], cc[3]);
            unpack2(pu0, uu[0], uu[1]); unpack2(pu1, uu[2], uu[3]);
#pragma unroll
            for (int r = 0; r < R; r++) {
                float reset = sigmoidf_(rr[r]);
                float cand  = tanhf(reset * cc[r]);
                float upd   = sigmoidf_(uu[r] - 1.0f);
                float dold  = s_xd[(200 + u) * R + r];
                float dn    = upd * cand + (1.f - upd) * dold;
                s_dn[u * R + r] = dn;
                out[(((size_t)(row0 + r)) * NT + t) * OUTC + 180 + u] = dn;
            }
        }
        __syncthreads();

        // ---------- C/D fused: h = elu(dn@img_W+b) ; ho = elu(dn@obsW_d + pre_obs) ----------
        if (tid < NH) {
            const int j = tid;
            float ib = img_out_b[j];
            unsigned long long h0 = pack2(ib, ib), h1 = h0;
            size_t base = ((size_t)row0 * NT + t) * NH + j;
            unsigned long long o0 = pack2(g_pre_obs[base],
                                          g_pre_obs[base + (size_t)NT * NH]);
            unsigned long long o1 = pack2(g_pre_obs[base + 2 * (size_t)NT * NH],
                                          g_pre_obs[base + 3 * (size_t)NT * NH]);
#pragma unroll 4
            for (int k = 0; k < ND; k++) {
                ulonglong2 av = *(const ulonglong2*)&s_dn[k * R];
                float wi = img_out_W[k * NH + j];
                float wo = obs_out_W[k * NH + j];
                unsigned long long wiv = pack2(wi, wi);
                unsigned long long wov = pack2(wo, wo);
                h0 = fma2(av.x, wiv, h0);  h1 = fma2(av.y, wiv, h1);
                o0 = fma2(av.x, wov, o0);  o1 = fma2(av.y, wov, o1);
            }
            float v0, v1, v2, v3;
            unpack2(h0, v0, v1); unpack2(h1, v2, v3);
            s_h[j * R + 0] = eluf(v0); s_h[j * R + 1] = eluf(v1);
            s_h[j * R + 2] = eluf(v2); s_h[j * R + 3] = eluf(v3);
            unpack2(o0, v0, v1); unpack2(o1, v2, v3);
            s_ho[j * R + 0] = eluf(v0); s_ho[j * R + 1] = eluf(v1);
            s_ho[j * R + 2] = eluf(v2); s_ho[j * R + 3] = eluf(v3);
        }
        __syncthreads();

        // ---------- E/F: stat layers (60 cols each, run concurrently) ----------
        if (tid < 60) {
            const int u = tid;
            float b = ims_b[u];
            unsigned long long a0 = pack2(b, b), a1 = a0;
#pragma unroll 4
            for (int k = 0; k < NH; k++) {
                ulonglong2 av = *(const ulonglong2*)&s_h[k * R];
                float wv_ = ims_W[k * 60 + u];
                unsigned long long wv = pack2(wv_, wv_);
                a0 = fma2(av.x, wv, a0);
                a1 = fma2(av.y, wv, a1);
            }
            float v0, v1, v2, v3;
            unpack2(a0, v0, v1); unpack2(a1, v2, v3);
            s_stat_pr[u * R + 0] = v0; s_stat_pr[u * R + 1] = v1;
            s_stat_pr[u * R + 2] = v2; s_stat_pr[u * R + 3] = v3;
        } else if (tid >= 64 && tid < 124) {
            const int u = tid - 64;
            float b = obs_b[u];
            unsigned long long a0 = pack2(b, b), a1 = a0;
#pragma unroll 4
            for (int k = 0; k < NH; k++) {
                ulonglong2 av = *(const ulonglong2*)&s_ho[k * R];
                float wv_ = obs_W[k * 60 + u];
                unsigned long long wv = pack2(wv_, wv_);
                a0 = fma2(av.x, wv, a0);
                a1 = fma2(av.y, wv, a1);
            }
            float v0, v1, v2, v3;
            unpack2(a0, v0, v1); unpack2(a1, v2, v3);
            s_stat_po[u * R + 0] = v0; s_stat_po[u * R + 1] = v1;
            s_stat_po[u * R + 2] = v2; s_stat_po[u * R + 3] = v3;
        }
        __syncthreads();

        // ---------- finalize: sample, write outputs, carry update ----------
        if (tid < NS) {
            const int u = tid;
#pragma unroll
            for (int r = 0; r < R; r++) {
                float m  = s_stat_pr[u * R + r];
                float sd = softplusf_(s_stat_pr[(NS + u) * R + r]) + 0.1f;
                size_t bt = ((size_t)(row0 + r)) * NT + t;
                float nz = noise_prior[bt * NS + u];
                size_t ob = bt * OUTC;
                out[ob + 120 + u] = m;
                out[ob + 150 + u] = sd;
                out[ob +  90 + u] = m + sd * nz;   // stoch_pr
            }
        } else if (tid >= 32 && tid < 32 + NS) {
            const int u = tid - 32;
#pragma unroll
            for (int r = 0; r < R; r++) {
                float m  = s_stat_po[u * R + r];
                float sd = softplusf_(s_stat_po[(NS + u) * R + r]) + 0.1f;
                size_t bt = ((size_t)(row0 + r)) * NT + t;
                float nz = noise_post[bt * NS + u];
                float st = m + sd * nz;            // stoch_po
                size_t ob = bt * OUTC;
                out[ob + 30 + u] = m;
                out[ob + 60 + u] = sd;
                out[ob +  0 + u] = st;
                s_stoch[u * R + r] = st;
            }
        } else if (tid >= 64) {
            // copy deter_new -> deter slot of s_xd for next step (float4 = 4 rows)
            for (int q = tid - 64; q < ND; q += 192)
                ((float4*)(s_xd + 200 * R))[q] = ((const float4*)s_dn)[q];
        }
        __syncthreads();
    }
}

// =====================================================================
extern "C" void kernel_launch(void* const* d_in, const int* in_sizes, int n_in,
                              void* d_out, int out_size) {
    const float* embed       = (const float*)d_in[0];
    const float* action      = (const float*)d_in[1];
    const float* noise_prior = (const float*)d_in[2];
    const float* noise_post  = (const float*)d_in[3];
    const float* inp_W       = (const float*)d_in[4];
    const float* inp_b       = (const float*)d_in[5];
    const float* gru_W       = (const float*)d_in[6];
    const float* gru_b       = (const float*)d_in[7];
    const float* img_out_W   = (const float*)d_in[8];
    const float* img_out_b   = (const float*)d_in[9];
    const float* ims_W       = (const float*)d_in[10];
    const float* ims_b       = (const float*)d_in[11];
    const float* obs_out_W   = (const float*)d_in[12];
    const float* obs_out_b   = (const float*)d_in[13];
    const float* obs_W       = (const float*)d_in[14];
    const float* obs_b       = (const float*)d_in[15];
    float* out = (float*)d_out;

    precompute_kernel<<<(NB * NT) / PRE_ROWS, 224>>>(embed, action, obs_out_W, obs_out_b,
                                                     inp_W, inp_b);
    scan_kernel<<<NB / R, 256>>>(noise_prior, noise_post, inp_W,
                                 gru_W, gru_b, img_out_W, img_out_b,
                                 ims_W, ims_b, obs_out_W, obs_W, obs_b, out);
}

// round 3
// speedup vs baseline: 1.4602x; 1.4602x over previous
#include <cuda_runtime.h>
#include <math.h>

#define NB 512
#define NT 64
#define NS 30
#define ND 200
#define NH 200
#define NA 12
#define NE 1024
#define OUTC 380
#define R 4

typedef unsigned long long ull;

// ---------------- device-global scratch (allocation-free rule) ----------------
__device__ float4 g_gru4[400 * 200];   // (w_r, w_c, w_u, 0) at [k][u]
__device__ float2 g_io2 [200 * 200];   // (img_out_W[k][j], obs_out_W[k][j])
__device__ float2 g_ef2 [200 * 60];    // (ims_W[k][u], obs_W[k][u])
__device__ float  g_pre_inp[NB * NT * NH];
__device__ float  g_pre_obs[NB * NT * NH];

// ---------------- packed f32x2 helpers ----------------
__device__ __forceinline__ ull pack2(float lo, float hi) {
    ull r; asm("mov.b64 %0, {%1, %2};" : "=l"(r) : "f"(lo), "f"(hi)); return r;
}
__device__ __forceinline__ void unpack2(ull v, float& lo, float& hi) {
    asm("mov.b64 {%0, %1}, %2;" : "=f"(lo), "=f"(hi) : "l"(v));
}
__device__ __forceinline__ ull fma2(ull a, ull b, ull c) {
    ull d; asm("fma.rn.f32x2 %0, %1, %2, %3;" : "=l"(d) : "l"(a), "l"(b), "l"(c)); return d;
}
__device__ __forceinline__ ull add2(ull a, ull b) {
    ull d; asm("add.rn.f32x2 %0, %1, %2;" : "=l"(d) : "l"(a), "l"(b)); return d;
}

// ---------------- math helpers ----------------
__device__ __forceinline__ float eluf(float z)      { return z > 0.f ? z : expm1f(z); }
__device__ __forceinline__ float sigmoidf_(float z) { return 1.f / (1.f + expf(-z)); }
__device__ __forceinline__ float softplusf_(float z){ return fmaxf(z, 0.f) + log1pf(expf(-fabsf(z))); }

// =====================================================================
// Kernel 0: build packed weight layouts (fp32, exact)
// =====================================================================
__global__ void convert_kernel(const float* __restrict__ gru_W,
                               const float* __restrict__ img_W,
                               const float* __restrict__ obs_out_W,
                               const float* __restrict__ ims_W,
                               const float* __restrict__ obs_W)
{
    int i = blockIdx.x * blockDim.x + threadIdx.x;
    if (i < 400 * 200) {
        int k = i / 200, u = i % 200;
        g_gru4[i] = make_float4(gru_W[k * 600 + u],
                                gru_W[k * 600 + 200 + u],
                                gru_W[k * 600 + 400 + u], 0.f);
    }
    if (i < 200 * 200) {
        g_io2[i] = make_float2(img_W[i], obs_out_W[i]);
    }
    if (i < 200 * 60) {
        int k = i / 60, u = i % 60;
        g_ef2[i] = make_float2(ims_W[k * 60 + u], obs_W[k * 60 + u]);
    }
}

// =====================================================================
// Kernel 1: precompute (unchanged from R1)
// =====================================================================
#define PRE_ROWS 32
#define PRE_KC   256
#define PRE_PAD  36

__global__ void __launch_bounds__(224) precompute_kernel(
    const float* __restrict__ embed,
    const float* __restrict__ action,
    const float* __restrict__ obs_out_W,
    const float* __restrict__ obs_out_b,
    const float* __restrict__ inp_W,
    const float* __restrict__ inp_b)
{
    __shared__ __align__(16) float s_aT[PRE_KC * PRE_PAD];
    __shared__ float s_act[PRE_ROWS * NA];

    const int bt0 = blockIdx.x * PRE_ROWS;
    const int tid = threadIdx.x;
    const int j   = tid;

    ull acc[16];
    {
        float b = (j < NH) ? obs_out_b[j] : 0.f;
        ull bb = pack2(b, b);
#pragma unroll
        for (int i = 0; i < 16; i++) acc[i] = bb;
    }

    const float* W2 = obs_out_W + (size_t)ND * NH;

    for (int kc = 0; kc < NE; kc += PRE_KC) {
        __syncthreads();
        for (int idx = tid; idx < PRE_ROWS * PRE_KC; idx += blockDim.x) {
            int rr = idx / PRE_KC;
            int kk = idx % PRE_KC;
            s_aT[kk * PRE_PAD + rr] = embed[(size_t)(bt0 + rr) * NE + kc + kk];
        }
        __syncthreads();

        if (j < NH) {
#pragma unroll 2
            for (int kk = 0; kk < PRE_KC; kk++) {
                float w = W2[(size_t)(kc + kk) * NH + j];
                ull wv = pack2(w, w);
                const ulonglong2* ap = (const ulonglong2*)&s_aT[kk * PRE_PAD];
#pragma unroll
                for (int q = 0; q < 8; q++) {
                    ulonglong2 a = ap[q];
                    acc[2 * q]     = fma2(a.x, wv, acc[2 * q]);
                    acc[2 * q + 1] = fma2(a.y, wv, acc[2 * q + 1]);
                }
            }
        }
    }

    if (j < NH) {
#pragma unroll
        for (int q = 0; q < 8; q++) {
            float v0, v1, v2, v3;
            unpack2(acc[2 * q],     v0, v1);
            unpack2(acc[2 * q + 1], v2, v3);
            g_pre_obs[(size_t)(bt0 + 4 * q + 0) * NH + j] = v0;
            g_pre_obs[(size_t)(bt0 + 4 * q + 1) * NH + j] = v1;
            g_pre_obs[(size_t)(bt0 + 4 * q + 2) * NH + j] = v2;
            g_pre_obs[(size_t)(bt0 + 4 * q + 3) * NH + j] = v3;
        }
    }

    __syncthreads();
    for (int idx = tid; idx < PRE_ROWS * NA; idx += blockDim.x) {
        int rr = idx / NA, kk = idx % NA;
        s_act[idx] = action[(size_t)(bt0 + rr) * NA + kk];
    }
    __syncthreads();

    if (j < NH) {
        float ib = inp_b[j];
        float wA[NA];
#pragma unroll
        for (int k = 0; k < NA; k++) wA[k] = inp_W[(NS + k) * NH + j];
        for (int rr = 0; rr < PRE_ROWS; rr++) {
            float a = ib;
#pragma unroll
            for (int k = 0; k < NA; k++) a = fmaf(s_act[rr * NA + k], wA[k], a);
            g_pre_inp[(size_t)(bt0 + rr) * NH + j] = a;
        }
    }
}

// =====================================================================
// Kernel 2: sequential scan. 128 CTAs x 4 rows, 512 threads, k-split.
// =====================================================================
__global__ void __launch_bounds__(512) scan_kernel(
    const float* __restrict__ noise_prior,
    const float* __restrict__ noise_post,
    const float* __restrict__ inp_W,
    const float* __restrict__ gru_b,
    const float* __restrict__ img_out_b,
    const float* __restrict__ ims_b,
    const float* __restrict__ obs_b,
    float* __restrict__ out)
{
    __shared__ __align__(16) float s_xd[400 * R];   // x (0..199), deter (200..399)
    __shared__ __align__(16) float s_dn[200 * R];
    __shared__ __align__(16) float s_h [200 * R];
    __shared__ __align__(16) float s_ho[200 * R];
    __shared__ __align__(16) float s_po[200 * R];   // prefetched pre_obs
    __shared__ __align__(16) float s_stoch[32 * R];
    __shared__ __align__(16) float s_stat_pr[60 * R];
    __shared__ __align__(16) float s_stat_po[60 * R];
    __shared__ __align__(16) ull s_gp [200 * 6];    // GRU partials (half 1)
    __shared__ __align__(16) ull s_iop[200 * 4];    // io partials (half 1)
    __shared__ __align__(16) ull s_efp[60 * 3 * 4]; // ef partials (quarters 1..3)

    const int tid  = threadIdx.x;
    const int row0 = blockIdx.x * R;

    for (int i = tid; i < 400 * R; i += 512) s_xd[i] = 0.f;
    for (int i = tid; i < 32 * R;  i += 512) s_stoch[i] = 0.f;
    __syncthreads();

    const int h400 = tid / 200;        // 0/1 for tid<400
    const int u400 = tid % 200;

    for (int t = 0; t < NT; t++) {
        // ========== Phase A: x = elu(stoch @ inp_W[:30] + pre_inp); prefetch pre_obs ==========
        if (tid < 200) {
            const int j = tid;
            size_t base = ((size_t)row0 * NT + t) * NH + j;
            ull a0 = pack2(g_pre_inp[base], g_pre_inp[base + (size_t)NT * NH]);
            ull a1 = pack2(g_pre_inp[base + 2 * (size_t)NT * NH],
                           g_pre_inp[base + 3 * (size_t)NT * NH]);
#pragma unroll
            for (int k = 0; k < NS; k++) {
                float w = inp_W[k * NH + j];
                ull wv = pack2(w, w);
                ulonglong2 av = *(const ulonglong2*)&s_stoch[k * R];
                a0 = fma2(av.x, wv, a0);
                a1 = fma2(av.y, wv, a1);
            }
            float y0, y1, y2, y3;
            unpack2(a0, y0, y1); unpack2(a1, y2, y3);
            s_xd[j * R + 0] = eluf(y0);
            s_xd[j * R + 1] = eluf(y1);
            s_xd[j * R + 2] = eluf(y2);
            s_xd[j * R + 3] = eluf(y3);
        } else if (tid >= 224 && tid < 424) {
            const int j = tid - 224;
            size_t base = ((size_t)row0 * NT + t) * NH + j;
            s_po[j * R + 0] = g_pre_obs[base];
            s_po[j * R + 1] = g_pre_obs[base + (size_t)NT * NH];
            s_po[j * R + 2] = g_pre_obs[base + 2 * (size_t)NT * NH];
            s_po[j * R + 3] = g_pre_obs[base + 3 * (size_t)NT * NH];
        }
        __syncthreads();

        // ========== Phase B: GRU, k-split x2 over 400 threads ==========
        ull pr0 = 0, pr1 = 0, pc0 = 0, pc1 = 0, pu0 = 0, pu1 = 0;
        if (tid < 400) {
            if (h400 == 0) {
                float br = gru_b[u400], bc = gru_b[200 + u400], bu = gru_b[400 + u400];
                pr0 = pack2(br, br); pr1 = pr0;
                pc0 = pack2(bc, bc); pc1 = pc0;
                pu0 = pack2(bu, bu); pu1 = pu0;
            }
            const float4* wp = g_gru4 + h400 * 200 * 200 + u400;
            const ulonglong2* ap = (const ulonglong2*)s_xd + h400 * 200;
#pragma unroll 8
            for (int k = 0; k < 200; k++) {
                float4 w = wp[(size_t)k * 200];
                ulonglong2 av = ap[k];
                ull wr = pack2(w.x, w.x), wc = pack2(w.y, w.y), wu = pack2(w.z, w.z);
                pr0 = fma2(av.x, wr, pr0);  pr1 = fma2(av.y, wr, pr1);
                pc0 = fma2(av.x, wc, pc0);  pc1 = fma2(av.y, wc, pc1);
                pu0 = fma2(av.x, wu, pu0);  pu1 = fma2(av.y, wu, pu1);
            }
            if (h400 == 1) {
                ull* sp = &s_gp[u400 * 6];
                sp[0] = pr0; sp[1] = pr1; sp[2] = pc0;
                sp[3] = pc1; sp[4] = pu0; sp[5] = pu1;
            }
        }
        __syncthreads();

        if (tid < 200) {
            const int u = tid;
            const ull* sp = &s_gp[u * 6];
            pr0 = add2(pr0, sp[0]); pr1 = add2(pr1, sp[1]);
            pc0 = add2(pc0, sp[2]); pc1 = add2(pc1, sp[3]);
            pu0 = add2(pu0, sp[4]); pu1 = add2(pu1, sp[5]);
            float rr[R], cc[R], uu[R];
            unpack2(pr0, rr[0], rr[1]); unpack2(pr1, rr[2], rr[3]);
            unpack2(pc0, cc[0], cc[1]); unpack2(pc1, cc[2], cc[3]);
            unpack2(pu0, uu[0], uu[1]); unpack2(pu1, uu[2], uu[3]);
#pragma unroll
            for (int r = 0; r < R; r++) {
                float reset = sigmoidf_(rr[r]);
                float cand  = tanhf(reset * cc[r]);
                float upd   = sigmoidf_(uu[r] - 1.0f);
                float dold  = s_xd[(200 + u) * R + r];
                float dn    = upd * cand + (1.f - upd) * dold;
                s_dn[u * R + r] = dn;
                out[(((size_t)(row0 + r)) * NT + t) * OUTC + 180 + u] = dn;
            }
        }
        __syncthreads();

        // ========== Phase C/D: h & ho, k-split x2 over 400 threads ==========
        ull ch0 = 0, ch1 = 0, co0 = 0, co1 = 0;
        if (tid < 400) {
            if (h400 == 0) {
                float ib = img_out_b[u400];
                ch0 = pack2(ib, ib); ch1 = ch0;
            }
            const float2* wp = g_io2 + h400 * 100 * 200 + u400;
            const ulonglong2* ap = (const ulonglong2*)s_dn + h400 * 100;
#pragma unroll 8
            for (int k = 0; k < 100; k++) {
                float2 w = wp[(size_t)k * 200];
                ulonglong2 av = ap[k];
                ull wi = pack2(w.x, w.x), wo = pack2(w.y, w.y);
                ch0 = fma2(av.x, wi, ch0);  ch1 = fma2(av.y, wi, ch1);
                co0 = fma2(av.x, wo, co0);  co1 = fma2(av.y, wo, co1);
            }
            if (h400 == 1) {
                ull* sp = &s_iop[u400 * 4];
                sp[0] = ch0; sp[1] = ch1; sp[2] = co0; sp[3] = co1;
            }
        }
        __syncthreads();

        if (tid < 200) {
            const int j = tid;
            const ull* sp = &s_iop[j * 4];
            ch0 = add2(ch0, sp[0]); ch1 = add2(ch1, sp[1]);
            co0 = add2(co0, sp[2]); co1 = add2(co1, sp[3]);
            ulonglong2 po = *(const ulonglong2*)&s_po[j * R];
            co0 = add2(co0, po.x);  co1 = add2(co1, po.y);
            float v0, v1, v2, v3;
            unpack2(ch0, v0, v1); unpack2(ch1, v2, v3);
            s_h[j * R + 0] = eluf(v0); s_h[j * R + 1] = eluf(v1);
            s_h[j * R + 2] = eluf(v2); s_h[j * R + 3] = eluf(v3);
            unpack2(co0, v0, v1); unpack2(co1, v2, v3);
            s_ho[j * R + 0] = eluf(v0); s_ho[j * R + 1] = eluf(v1);
            s_ho[j * R + 2] = eluf(v2); s_ho[j * R + 3] = eluf(v3);
        }
        __syncthreads();

        // ========== Phase E/F: stat layers, k-split x4 over 240 threads ==========
        ull ea0 = 0, ea1 = 0, eb0 = 0, eb1 = 0;
        if (tid < 240) {
            const int q = tid / 60, u = tid % 60;
            if (q == 0) {
                float ba = ims_b[u], bb = obs_b[u];
                ea0 = pack2(ba, ba); ea1 = ea0;
                eb0 = pack2(bb, bb); eb1 = eb0;
            }
            const float2* wp = g_ef2 + q * 50 * 60 + u;
            const ulonglong2* hp = (const ulonglong2*)s_h  + q * 50;
            const ulonglong2* op = (const ulonglong2*)s_ho + q * 50;
#pragma unroll 8
            for (int k = 0; k < 50; k++) {
                float2 w = wp[(size_t)k * 60];
                ulonglong2 ah = hp[k];
                ulonglong2 ao = op[k];
                ull wi = pack2(w.x, w.x), wo = pack2(w.y, w.y);
                ea0 = fma2(ah.x, wi, ea0);  ea1 = fma2(ah.y, wi, ea1);
                eb0 = fma2(ao.x, wo, eb0);  eb1 = fma2(ao.y, wo, eb1);
            }
            if (q > 0) {
                ull* sp = &s_efp[((q - 1) * 60 + u) * 4];
                sp[0] = ea0; sp[1] = ea1; sp[2] = eb0; sp[3] = eb1;
            }
        }
        __syncthreads();

        if (tid < 60) {
            const int u = tid;
#pragma unroll
            for (int qq = 0; qq < 3; qq++) {
                const ull* sp = &s_efp[(qq * 60 + u) * 4];
                ea0 = add2(ea0, sp[0]); ea1 = add2(ea1, sp[1]);
                eb0 = add2(eb0, sp[2]); eb1 = add2(eb1, sp[3]);
            }
            float v0, v1, v2, v3;
            unpack2(ea0, v0, v1); unpack2(ea1, v2, v3);
            s_stat_pr[u * R + 0] = v0; s_stat_pr[u * R + 1] = v1;
            s_stat_pr[u * R + 2] = v2; s_stat_pr[u * R + 3] = v3;
            unpack2(eb0, v0, v1); unpack2(eb1, v2, v3);
            s_stat_po[u * R + 0] = v0; s_stat_po[u * R + 1] = v1;
            s_stat_po[u * R + 2] = v2; s_stat_po[u * R + 3] = v3;
        }
        __syncthreads();

        // ========== finalize: sample, outputs, carry update ==========
        if (tid < NS) {
            const int u = tid;
#pragma unroll
            for (int r = 0; r < R; r++) {
                float m  = s_stat_pr[u * R + r];
                float sd = softplusf_(s_stat_pr[(NS + u) * R + r]) + 0.1f;
                size_t bt = ((size_t)(row0 + r)) * NT + t;
                float nz = noise_prior[bt * NS + u];
                size_t ob = bt * OUTC;
                out[ob + 120 + u] = m;
                out[ob + 150 + u] = sd;
                out[ob +  90 + u] = m + sd * nz;
            }
        } else if (tid >= 32 && tid < 32 + NS) {
            const int u = tid - 32;
#pragma unroll
            for (int r = 0; r < R; r++) {
                float m  = s_stat_po[u * R + r];
                float sd = softplusf_(s_stat_po[(NS + u) * R + r]) + 0.1f;
                size_t bt = ((size_t)(row0 + r)) * NT + t;
                float nz = noise_post[bt * NS + u];
                float st = m + sd * nz;
                size_t ob = bt * OUTC;
                out[ob + 30 + u] = m;
                out[ob + 60 + u] = sd;
                out[ob +  0 + u] = st;
                s_stoch[u * R + r] = st;
            }
        } else if (tid >= 64) {
            for (int q = tid - 64; q < ND; q += 448)
                ((float4*)(s_xd + 200 * R))[q] = ((const float4*)s_dn)[q];
        }
        __syncthreads();
    }
}

// =====================================================================
extern "C" void kernel_launch(void* const* d_in, const int* in_sizes, int n_in,
                              void* d_out, int out_size) {
    const float* embed       = (const float*)d_in[0];
    const float* action      = (const float*)d_in[1];
    const float* noise_prior = (const float*)d_in[2];
    const float* noise_post  = (const float*)d_in[3];
    const float* inp_W       = (const float*)d_in[4];
    const float* inp_b       = (const float*)d_in[5];
    const float* gru_W       = (const float*)d_in[6];
    const float* gru_b       = (const float*)d_in[7];
    const float* img_out_W   = (const float*)d_in[8];
    const float* img_out_b   = (const float*)d_in[9];
    const float* ims_W       = (const float*)d_in[10];
    const float* ims_b       = (const float*)d_in[11];
    const float* obs_out_W   = (const float*)d_in[12];
    const float* obs_out_b   = (const float*)d_in[13];
    const float* obs_W       = (const float*)d_in[14];
    const float* obs_b       = (const float*)d_in[15];
    float* out = (float*)d_out;

    convert_kernel<<<(400 * 200 + 255) / 256, 256>>>(gru_W, img_out_W, obs_out_W,
                                                     ims_W, obs_W);
    precompute_kernel<<<(NB * NT) / PRE_ROWS, 224>>>(embed, action, obs_out_W, obs_out_b,
                                                     inp_W, inp_b);
    scan_kernel<<<NB / R, 512>>>(noise_prior, noise_post, inp_W,
                                 gru_b, img_out_b, ims_b, obs_b, out);
}